// round 1
// baseline (speedup 1.0000x reference)
#include <cuda_runtime.h>

#define BSZ 32
#define CCH 256
#define NPX 4096
#define TC  32
#define TN  32
#define KB  8
#define REGF 0.01f

// ---------------------------------------------------------------------------
// packed fp32x2 FMA (Blackwell): 2 FMAs per instruction. ptxas never emits
// this from C++ (SASS_QUICKREF "patterns absent"), so inline PTX.
// ---------------------------------------------------------------------------
__device__ __forceinline__ void ffma2(unsigned long long& acc,
                                      unsigned long long a,
                                      unsigned long long b) {
    asm("fma.rn.f32x2 %0, %1, %2, %0;" : "+l"(acc) : "l"(a), "l"(b));
}

// ---------------------------------------------------------------------------
// Kernel 1: mean over batch. x: [B, C, N], mean: [C, N]. float4 vectorized.
// ---------------------------------------------------------------------------
__global__ void mvg_mean_kernel(const float* __restrict__ x,
                                float* __restrict__ mean) {
    int idx = blockIdx.x * blockDim.x + threadIdx.x;   // over C*N/4
    const float4* x4 = (const float4*)x;
    float4 s = make_float4(0.f, 0.f, 0.f, 0.f);
    const int stride = CCH * NPX / 4;
#pragma unroll
    for (int b = 0; b < BSZ; b++) {
        float4 v = x4[b * stride + idx];
        s.x += v.x; s.y += v.y; s.z += v.z; s.w += v.w;
    }
    const float inv = 1.0f / BSZ;
    s.x *= inv; s.y *= inv; s.z *= inv; s.w *= inv;
    ((float4*)mean)[idx] = s;
}

// ---------------------------------------------------------------------------
// Kernel 2: per-location covariance.
//   cov[c,d,n] = sum_b (x[b,c,n]-mean[c,n])*(x[b,d,n]-mean[d,n]) / (B-1)
//               + REG * (c==d)
// Tiling: block = (32 c-rows) x (32 d-rows) x (32 n).
// Only upper-triangular tile pairs are computed; off-diagonal pairs write
// both [c,d,n] and the mirrored [d,c,n].
// Thread microtile: 8c x 8d x 2n as packed f32x2 accumulators.
// ---------------------------------------------------------------------------
__global__ __launch_bounds__(256, 1)
void mvg_cov_kernel(const float* __restrict__ x,
                    const float* __restrict__ mean,
                    float* __restrict__ cov) {
    // decode upper-triangular tile pair (ti <= tj) from blockIdx.x in [0,36)
    int rem = blockIdx.x;
    int ti = 0, row = 8;
    while (rem >= row) { rem -= row; row--; ti++; }
    const int tj = ti + rem;
    const bool diag = (ti == tj);
    const int n0 = blockIdx.y * TN;

    // dynamic smem layout (floats):
    // [0      .. 8192 )  buf0 c-tile  (KB*TC*TN)
    // [8192   .. 16384)  buf0 d-tile
    // [16384  .. 24576)  buf1 c-tile
    // [24576  .. 32768)  buf1 d-tile
    // [32768  .. 33792)  mean c-tile (TC*TN)
    // [33792  .. 34816)  mean d-tile
    extern __shared__ float sm[];
    float* buf_c[2] = { sm,         sm + 16384 };
    float* buf_d[2] = { sm + 8192,  sm + 24576 };
    float* mc = sm + 32768;
    float* md = sm + 33792;

    const int tid = threadIdx.x;
    const int tn  = tid & 15;        // n-pair index (covers n0 + 2*tn, +1)
    const int tcd = tid >> 4;
    const int tc  = tcd & 3;         // 8 c-rows each
    const int td  = tcd >> 2;        // 8 d-rows each

    // ---- load mean tiles (TC*TN floats each = 256 float4) ----
    {
        int c  = tid >> 3;           // 0..31
        int nn = (tid & 7) << 2;     // 0,4,...,28
        *(float4*)&mc[c * TN + nn] =
            *(const float4*)&mean[(ti * TC + c) * NPX + n0 + nn];
        *(float4*)&md[c * TN + nn] =
            *(const float4*)&mean[(tj * TC + c) * NPX + n0 + nn];
    }
    __syncthreads();

    unsigned long long acc[8][8];
#pragma unroll
    for (int i = 0; i < 8; i++)
#pragma unroll
        for (int j = 0; j < 8; j++) acc[i][j] = 0ull;

    // ---- chunk loader: KB b-slices of both tiles, mean-subtracted ----
    auto load_chunk = [&](int buf, int kb) {
        float* dc = buf_c[buf];
        float* dd = buf_d[buf];
#pragma unroll
        for (int r = 0; r < 8; r++) {
            int f  = r * 256 + tid;          // 0..2047
            int bb = f >> 8;                 // 0..7
            int c  = (f >> 3) & 31;          // 0..31
            int nn = (f & 7) << 2;           // 0..28
            int so = (bb * TC + c) * TN + nn;
            float4 mv = *(const float4*)&mc[c * TN + nn];
            float4 v  = *(const float4*)&x[((kb + bb) * CCH + ti * TC + c) * NPX + n0 + nn];
            v.x -= mv.x; v.y -= mv.y; v.z -= mv.z; v.w -= mv.w;
            *(float4*)&dc[so] = v;
            if (!diag) {
                float4 mw = *(const float4*)&md[c * TN + nn];
                float4 w  = *(const float4*)&x[((kb + bb) * CCH + tj * TC + c) * NPX + n0 + nn];
                w.x -= mw.x; w.y -= mw.y; w.z -= mw.z; w.w -= mw.w;
                *(float4*)&dd[so] = w;
            }
        }
    };

    load_chunk(0, 0);
    __syncthreads();

    int buf = 0;
#pragma unroll
    for (int k = 0; k < BSZ / KB; k++) {
        if (k < BSZ / KB - 1) load_chunk(buf ^ 1, (k + 1) * KB);

        const float* pc = buf_c[buf];
        const float* pd = diag ? buf_c[buf] : buf_d[buf];
#pragma unroll
        for (int bb = 0; bb < KB; bb++) {
            unsigned long long av[8], bv[8];
#pragma unroll
            for (int i = 0; i < 8; i++)
                av[i] = *(const unsigned long long*)
                        &pc[(bb * TC + tc * 8 + i) * TN + tn * 2];
#pragma unroll
            for (int j = 0; j < 8; j++)
                bv[j] = *(const unsigned long long*)
                        &pd[(bb * TC + td * 8 + j) * TN + tn * 2];
#pragma unroll
            for (int i = 0; i < 8; i++)
#pragma unroll
                for (int j = 0; j < 8; j++)
                    ffma2(acc[i][j], av[i], bv[j]);
        }
        __syncthreads();
        buf ^= 1;
    }

    // ---- epilogue: scale, regularize diagonal, write (and mirror) ----
    const float scale = 1.0f / (BSZ - 1);
    const int n = n0 + tn * 2;
#pragma unroll
    for (int i = 0; i < 8; i++) {
        int c = ti * TC + tc * 8 + i;
#pragma unroll
        for (int j = 0; j < 8; j++) {
            int d = tj * TC + td * 8 + j;
            unsigned long long a = acc[i][j];
            float lo = __uint_as_float((unsigned)(a & 0xffffffffull)) * scale;
            float hi = __uint_as_float((unsigned)(a >> 32)) * scale;
            if (c == d) { lo += REGF; hi += REGF; }
            float2 out = make_float2(lo, hi);
            *(float2*)&cov[((size_t)c * CCH + d) * NPX + n] = out;
            if (!diag)
                *(float2*)&cov[((size_t)d * CCH + c) * NPX + n] = out;
        }
    }
}

// ---------------------------------------------------------------------------
extern "C" void kernel_launch(void* const* d_in, const int* in_sizes, int n_in,
                              void* d_out, int out_size) {
    const float* x = (const float*)d_in[0];
    float* out  = (float*)d_out;
    float* mean = out;                          // [C, N]
    float* cov  = out + (size_t)CCH * NPX;      // [C, C, N]

    // mean: C*N/4 float4 elements, 256 threads/block
    mvg_mean_kernel<<<(CCH * NPX / 4) / 256, 256>>>(x, mean);

    // cov: 36 upper-triangular tile pairs x 128 n-tiles
    static bool attr_set = false;
    const int smem_bytes = 34816 * 4;           // 136 KB
    if (!attr_set) {
        cudaFuncSetAttribute(mvg_cov_kernel,
                             cudaFuncAttributeMaxDynamicSharedMemorySize,
                             smem_bytes);
        attr_set = true;
    }
    dim3 grid(36, NPX / TN);
    mvg_cov_kernel<<<grid, 256, smem_bytes>>>(x, mean, cov);
}

// round 2
// speedup vs baseline: 1.1792x; 1.1792x over previous
#include <cuda_runtime.h>

#define BSZ 32
#define CCH 256
#define NPX 4096
#define TC  32
#define TN  32
#define KB  8
#define REGF 0.01f

// ---------------------------------------------------------------------------
// packed fp32x2 FMA (Blackwell): 2 FMAs per instruction; ptxas never emits
// this from C++ (SASS_QUICKREF "patterns absent"), so inline PTX.
// ---------------------------------------------------------------------------
__device__ __forceinline__ void ffma2(unsigned long long& acc,
                                      unsigned long long a,
                                      unsigned long long b) {
    asm("fma.rn.f32x2 %0, %1, %2, %0;" : "+l"(acc) : "l"(a), "l"(b));
}

__device__ __forceinline__ unsigned smem_u32(const void* p) {
    return (unsigned)__cvta_generic_to_shared(p);
}
__device__ __forceinline__ void cp16(unsigned s, const float* g) {
    asm volatile("cp.async.cg.shared.global [%0], [%1], 16;" :: "r"(s), "l"(g));
}
#define CP_COMMIT() asm volatile("cp.async.commit_group;" ::: "memory")
#define CP_WAIT(n)  asm volatile("cp.async.wait_group %0;" :: "n"(n) : "memory")

// ---------------------------------------------------------------------------
// Kernel 1: mean over batch. x: [B, C, N], mean: [C, N]. float4 vectorized.
// ---------------------------------------------------------------------------
__global__ void mvg_mean_kernel(const float* __restrict__ x,
                                float* __restrict__ mean) {
    int idx = blockIdx.x * blockDim.x + threadIdx.x;   // over C*N/4
    const float4* x4 = (const float4*)x;
    float4 s = make_float4(0.f, 0.f, 0.f, 0.f);
    const int stride = CCH * NPX / 4;
#pragma unroll
    for (int b = 0; b < BSZ; b++) {
        float4 v = x4[b * stride + idx];
        s.x += v.x; s.y += v.y; s.z += v.z; s.w += v.w;
    }
    const float inv = 1.0f / BSZ;
    s.x *= inv; s.y *= inv; s.z *= inv; s.w *= inv;
    ((float4*)mean)[idx] = s;
}

// ---------------------------------------------------------------------------
// Kernel 2: per-location covariance via raw second moment:
//   cov[c,d,n] = (sum_b x[b,c,n]*x[b,d,n] - B*m[c,n]*m[d,n]) / (B-1)
//              + REG * (c==d)
// Block = (32 c) x (32 d) x (32 n), upper-triangular tile pairs only,
// mirrored writes. Thread microtile: 8c x 8d x 2n packed f32x2.
// Staging: cp.async, 3 buffers, 2 chunks in flight.
// ---------------------------------------------------------------------------
__global__ __launch_bounds__(256, 1)
void mvg_cov_kernel(const float* __restrict__ x,
                    const float* __restrict__ mean,
                    float* __restrict__ cov) {
    // decode upper-triangular tile pair (ti <= tj) from blockIdx.x in [0,36)
    int rem = blockIdx.x;
    int ti = 0, row = 8;
    while (rem >= row) { rem -= row; row--; ti++; }
    const int tj = ti + rem;
    const bool diag = (ti == tj);
    const int n0 = blockIdx.y * TN;

    // dynamic smem: 3 bufs x (c-tile 8192 + d-tile 8192 floats) = 192 KB
    extern __shared__ float sm[];

    const int tid = threadIdx.x;
    const int tn  = tid & 15;        // n-pair index (covers n0 + 2*tn, +1)
    const int tcd = tid >> 4;
    const int tc  = tcd & 3;         // 8 c-rows each
    const int td  = tcd >> 2;        // 4 groups of 8 d-rows

    // ---- stage chunk k (raw copy, no mean subtract) ----
    auto stage = [&](int k) {
        float* dst = sm + (k % 3) * 16384;
#pragma unroll
        for (int r = 0; r < 8; r++) {
            int f  = r * 256 + tid;          // 0..2047
            int bb = f >> 8;                 // 0..7
            int c  = (f >> 3) & 31;          // 0..31
            int nn = (f & 7) << 2;           // 0,4,...,28
            unsigned so = smem_u32(dst + (bb * TC + c) * TN + nn);
            cp16(so, &x[((size_t)(k * KB + bb) * CCH + ti * TC + c) * NPX + n0 + nn]);
            if (!diag)
                cp16(so + 8192 * 4,
                     &x[((size_t)(k * KB + bb) * CCH + tj * TC + c) * NPX + n0 + nn]);
        }
        CP_COMMIT();
    };

    unsigned long long acc[8][8];
#pragma unroll
    for (int i = 0; i < 8; i++)
#pragma unroll
        for (int j = 0; j < 8; j++) acc[i][j] = 0ull;

    auto compute = [&](int k) {
        const float* pc = sm + (k % 3) * 16384;
        const float* pd = diag ? pc : pc + 8192;
#pragma unroll
        for (int bb = 0; bb < KB; bb++) {
            unsigned long long av[8], bv[8];
#pragma unroll
            for (int i = 0; i < 8; i++)
                av[i] = *(const unsigned long long*)
                        &pc[(bb * TC + tc * 8 + i) * TN + tn * 2];
#pragma unroll
            for (int j = 0; j < 8; j++)
                bv[j] = *(const unsigned long long*)
                        &pd[(bb * TC + td * 8 + j) * TN + tn * 2];
#pragma unroll
            for (int i = 0; i < 8; i++)
#pragma unroll
                for (int j = 0; j < 8; j++)
                    ffma2(acc[i][j], av[i], bv[j]);
        }
    };

    // pipeline: 4 chunks, 3 buffers, up to 2 chunks ahead
    stage(0); stage(1); stage(2);
    CP_WAIT(2); __syncthreads();
    compute(0);
    __syncthreads();               // everyone done reading buf0
    stage(3);                      // into buf0
    CP_WAIT(2); __syncthreads();
    compute(1);
    CP_WAIT(1); __syncthreads();
    compute(2);
    CP_WAIT(0); __syncthreads();
    compute(3);

    // ---- epilogue: mean correction, scale, regularize, streaming writes ----
    const float scale = 1.0f / (BSZ - 1);
    const int n = n0 + tn * 2;
    float2 mcv[8], mdv[8];
#pragma unroll
    for (int i = 0; i < 8; i++)
        mcv[i] = *(const float2*)&mean[(size_t)(ti * TC + tc * 8 + i) * NPX + n];
#pragma unroll
    for (int j = 0; j < 8; j++)
        mdv[j] = *(const float2*)&mean[(size_t)(tj * TC + td * 8 + j) * NPX + n];

#pragma unroll
    for (int i = 0; i < 8; i++) {
        int c = ti * TC + tc * 8 + i;
#pragma unroll
        for (int j = 0; j < 8; j++) {
            int d = tj * TC + td * 8 + j;
            unsigned long long a = acc[i][j];
            float lo = __uint_as_float((unsigned)(a & 0xffffffffull));
            float hi = __uint_as_float((unsigned)(a >> 32));
            lo = (lo - (float)BSZ * mcv[i].x * mdv[j].x) * scale;
            hi = (hi - (float)BSZ * mcv[i].y * mdv[j].y) * scale;
            if (c == d) { lo += REGF; hi += REGF; }
            float2 out = make_float2(lo, hi);
            __stcs((float2*)&cov[((size_t)c * CCH + d) * NPX + n], out);
            if (!diag)
                __stcs((float2*)&cov[((size_t)d * CCH + c) * NPX + n], out);
        }
    }
}

// ---------------------------------------------------------------------------
extern "C" void kernel_launch(void* const* d_in, const int* in_sizes, int n_in,
                              void* d_out, int out_size) {
    const float* x = (const float*)d_in[0];
    float* out  = (float*)d_out;
    float* mean = out;                          // [C, N]
    float* cov  = out + (size_t)CCH * NPX;      // [C, C, N]

    mvg_mean_kernel<<<(CCH * NPX / 4) / 256, 256>>>(x, mean);

    static bool attr_set = false;
    const int smem_bytes = 3 * 16384 * 4;       // 192 KB
    if (!attr_set) {
        cudaFuncSetAttribute(mvg_cov_kernel,
                             cudaFuncAttributeMaxDynamicSharedMemorySize,
                             smem_bytes);
        attr_set = true;
    }
    dim3 grid(36, NPX / TN);
    mvg_cov_kernel<<<grid, 256, smem_bytes>>>(x, mean, cov);
}